// round 14
// baseline (speedup 1.0000x reference)
#include <cuda_runtime.h>

// Problem constants
#define T_STEPS 168
#define IN_DIM  16
#define NH1     64
#define NH2     32
#define NG1     256   // 4*H1
#define NG2     128   // 4*H2
#define BATCH   4096

// Tiling: one wave — 147 CTAs on 148 SMs, 512 threads each
#define NB   28
#define BLK  512
#define GRID ((BATCH + NB - 1) / NB)   // 147

// Strides (floats): ≡ 0 mod 4 (float4 align), ≡ 4 mod 8 → conflict-free
// lane-strided LDS.128
#define W1_STRIDE  84    // 16 (x) + 64 (h1) + 4 pad
#define W2_STRIDE  100   // 64 (h1) + 32 (h2) + 4 pad
#define IN1_STRIDE 84    // [0:16]=x  [16:80]=h1
#define H2_STRIDE  36    // [0:32]=h2 + 4 pad

#define IN1_BUF (NB * IN1_STRIDE)    // 2352
#define H2_BUF  (NB * H2_STRIDE)     // 1008

#define OFF_W1   0
#define OFF_W2   (OFF_W1  + NG1 * W1_STRIDE)     // 21504
#define OFF_B1   (OFF_W2  + NG2 * W2_STRIDE)     // 34304
#define OFF_B2   (OFF_B1  + NG1)                 // 34560
#define OFF_WFC  (OFF_B2  + NG2)                 // 34688
#define OFF_IN1  (OFF_WFC + 32)                  // 34720  double buffer [2][28][84]
#define OFF_H2   (OFF_IN1 + 2 * IN1_BUF)         // 39424  double buffer [2][28][36]
#define SMEM_FLOATS (OFF_H2 + 2 * H2_BUF)        // 41440 floats ≈ 166 KB

typedef unsigned long long u64;

__device__ __forceinline__ void fma2(u64& d, u64 a, u64 b) {
    asm("fma.rn.f32x2 %0, %1, %2, %0;" : "+l"(d) : "l"(a), "l"(b));
}
__device__ __forceinline__ u64 pack2(float lo, float hi) {
    u64 r; asm("mov.b64 %0, {%1, %2};" : "=l"(r) : "f"(lo), "f"(hi)); return r;
}
__device__ __forceinline__ float pairsum(u64 v) {
    float lo, hi;
    asm("mov.b64 {%0, %1}, %2;" : "=f"(lo), "=f"(hi) : "l"(v));
    return lo + hi;
}
// single-MUFU activations (MUFU.TANH)
__device__ __forceinline__ float tanh_(float v) {
    float r; asm("tanh.approx.f32 %0, %1;" : "=f"(r) : "f"(v)); return r;
}
__device__ __forceinline__ float sigm_(float v) {
    return fmaf(0.5f, tanh_(0.5f * v), 0.5f);
}

extern __shared__ float smem[];

__global__ __launch_bounds__(BLK, 1)
void lstm2_fused_kernel(const float* __restrict__ x,
                        const float* __restrict__ Wih1, const float* __restrict__ Whh1,
                        const float* __restrict__ bih1, const float* __restrict__ bhh1,
                        const float* __restrict__ Wih2, const float* __restrict__ Whh2,
                        const float* __restrict__ bih2, const float* __restrict__ bhh2,
                        const float* __restrict__ Wfc,  const float* __restrict__ bfc,
                        float* __restrict__ out)
{
    const int tid = threadIdx.x;
    const int b0  = blockIdx.x * NB;

    float* sW1  = smem + OFF_W1;
    float* sW2  = smem + OFF_W2;
    float* sB1  = smem + OFF_B1;
    float* sB2  = smem + OFF_B2;
    float* sWfc = smem + OFF_WFC;
    float* sIn1 = smem + OFF_IN1;
    float* sH2  = smem + OFF_H2;

    // ---- weights into shared (combined [x;h] rows, padded strides) ----
    for (int i = tid; i < NG1 * W1_STRIDE; i += BLK) {
        int g = i / W1_STRIDE, k = i % W1_STRIDE;
        float v = 0.f;
        if (k < IN_DIM)            v = Wih1[g * IN_DIM + k];
        else if (k < IN_DIM + NH1) v = Whh1[g * NH1 + (k - IN_DIM)];
        sW1[i] = v;
    }
    for (int i = tid; i < NG2 * W2_STRIDE; i += BLK) {
        int g = i / W2_STRIDE, k = i % W2_STRIDE;
        float v = 0.f;
        if (k < NH1)            v = Wih2[g * NH1 + k];
        else if (k < NH1 + NH2) v = Whh2[g * NH2 + (k - NH1)];
        sW2[i] = v;
    }
    if (tid < NG1) sB1[tid] = bih1[tid] + bhh1[tid];
    if (tid < NG2) sB2[tid] = bih2[tid] + bhh2[tid];
    if (tid < NH2) sWfc[tid] = Wfc[tid];
    for (int i = tid; i < 2 * IN1_BUF; i += BLK) sIn1[i] = 0.f;
    for (int i = tid; i < 2 * H2_BUF;  i += BLK) sH2[i] = 0.f;

    const int lane = tid & 31;
    const int wid  = tid >> 5;

    // ---- L1 mapping (tid 0..255): warp = 16 units x 2 batch-groups.
    // Each weight row appears on TWO lanes (lane and lane^16) -> crossbar
    // dedup: 16 distinct 16B addrs = 2 wavefronts per LDS.128 (was 4).
    const int u1 = (wid & 3) * 16 + (lane & 15);      // 0..63
    const int q  = ((wid >> 2) & 1) * 2 + (lane >> 4); // 0..3
    const float* w1i = sW1 + u1 * W1_STRIDE;
    const float* w1f = sW1 + (64 + u1) * W1_STRIDE;
    const float* w1g = sW1 + (128 + u1) * W1_STRIDE;
    const float* w1o = sW1 + (192 + u1) * W1_STRIDE;

    // ---- L2 mapping (tid 256..511): warp = 8 units x 2 sf x 2 batch-groups.
    // sf partner at lane^8 (same unit, same batch-group). Weight rows appear
    // on two lanes -> 2 wavefronts per LDS.128 (was 4).
    const int wid2 = wid & 7;                          // 0..7 within L2 half
    const int uf = (wid2 & 3) * 8 + (lane & 7);        // 0..31
    const int sf = (lane >> 3) & 1;
    const int qf = ((wid2 >> 2) & 1) * 2 + (lane >> 4); // 0..3
    const float* wA = sW2 + (uf + sf * 32) * W2_STRIDE;        // i or f
    const float* wB = sW2 + (uf + 64 + sf * 32) * W2_STRIDE;   // g or o

    // ---- x publishers: threads 256..367 (112), one float4 (b, k4) each ----
    const int  xi   = tid - 256;
    const bool xact = (tid >= 256) && (xi < NB * (IN_DIM / 4));  // 112
    const int  xb   = xi >> 2;
    const int  xk4  = xi & 3;
    const bool xval = xact && (b0 + xb) < BATCH;
    const float* xptr = xval ? (x + ((long)(b0 + xb) * T_STEPS) * IN_DIM + xk4 * 4)
                             : x;
    float4 xreg = make_float4(0.f, 0.f, 0.f, 0.f);
    if (xval) xreg = *(const float4*)xptr;

    __syncthreads();
    if (xact) *(float4*)&sIn1[xb * IN1_STRIDE + xk4 * 4] = xreg;   // x(0) -> buf0
    if (xval) xreg = *(const float4*)(xptr + IN_DIM);              // x(1)
    __syncthreads();

    // ---- bias reads — after barrier so init writes are visible ----
    const float bi1 = sB1[u1];
    const float bf1 = sB1[64 + u1];
    const float bg1 = sB1[128 + u1];
    const float bo1 = sB1[192 + u1];
    const float bbA = sB2[uf + sf * 32];
    const float bbB = sB2[uf + 64 + sf * 32];

    float c1r[7], c2r[7];
#pragma unroll
    for (int j = 0; j < 7; j++) { c1r[j] = 0.f; c2r[j] = 0.f; }

    for (int t = 0; t <= T_STEPS; t++) {
        const float* rb = sIn1 + (t & 1) * IN1_BUF;        // x(t), h1(t-1)
        float*       wb = sIn1 + ((t + 1) & 1) * IN1_BUF;  // x(t+1), h1(t)

        if (tid < 256) {
            // ---- L1: all 4 gates of unit u1, 7 batches; cell update local ----
            if (t < T_STEPS) {
                u64 ai[7], af[7], ag[7], ao[7];
#pragma unroll
                for (int b = 0; b < 7; b++) {
                    ai[b] = pack2(bi1, 0.f);
                    af[b] = pack2(bf1, 0.f);
                    ag[b] = pack2(bg1, 0.f);
                    ao[b] = pack2(bo1, 0.f);
                }
                const float* in1q = rb + (q * 7) * IN1_STRIDE;
#pragma unroll 4
                for (int k4 = 0; k4 < (IN_DIM + NH1) / 4; k4++) {      // 20
                    const ulonglong2 wi = *(const ulonglong2*)(w1i + k4 * 4);
                    const ulonglong2 wf = *(const ulonglong2*)(w1f + k4 * 4);
                    const ulonglong2 wg = *(const ulonglong2*)(w1g + k4 * 4);
                    const ulonglong2 wo = *(const ulonglong2*)(w1o + k4 * 4);
#pragma unroll
                    for (int b = 0; b < 7; b++) {
                        const ulonglong2 h =
                            *(const ulonglong2*)(in1q + b * IN1_STRIDE + k4 * 4);
                        fma2(ai[b], wi.x, h.x); fma2(ai[b], wi.y, h.y);
                        fma2(af[b], wf.x, h.x); fma2(af[b], wf.y, h.y);
                        fma2(ag[b], wg.x, h.x); fma2(ag[b], wg.y, h.y);
                        fma2(ao[b], wo.x, h.x); fma2(ao[b], wo.y, h.y);
                    }
                }
                // epilogue: all gates local — update c1, write h1(t)
#pragma unroll
                for (int j = 0; j < 7; j++) {
                    const float i_ = sigm_(pairsum(ai[j]));
                    const float f_ = sigm_(pairsum(af[j]));
                    const float g_ = tanh_(pairsum(ag[j]));
                    const float o_ = sigm_(pairsum(ao[j]));
                    c1r[j] = fmaf(f_, c1r[j], i_ * g_);
                    wb[(q * 7 + j) * IN1_STRIDE + IN_DIM + u1] = o_ * tanh_(c1r[j]);
                }
            }
        } else {
            // ---- publish x(t+1) into write buffer; prefetch x(t+2) ----
            if (t < T_STEPS) {
                if (xact && (t + 1) < T_STEPS)
                    *(float4*)&wb[xb * IN1_STRIDE + xk4 * 4] = xreg;
                if (xval && (t + 2) < T_STEPS)
                    xreg = *(const float4*)(xptr + (long)(t + 2) * IN_DIM);
            }
            // ---- L2 fused: gates(t-1) + cell(t-1) ----
            if (t >= 1) {
                u64 accA[7], accB[7];
#pragma unroll
                for (int b = 0; b < 7; b++) {
                    accA[b] = pack2(bbA, 0.f);
                    accB[b] = pack2(bbB, 0.f);
                }
                const float* h1q = rb + (qf * 7) * IN1_STRIDE + IN_DIM;       // h1(t-1)
                const float* h2q = sH2 + (t & 1) * H2_BUF + (qf * 7) * H2_STRIDE; // h2(t-2)
#pragma unroll 4
                for (int k4 = 0; k4 < NH1 / 4; k4++) {                  // 16
                    const ulonglong2 wa = *(const ulonglong2*)(wA + k4 * 4);
                    const ulonglong2 wbv = *(const ulonglong2*)(wB + k4 * 4);
#pragma unroll
                    for (int b = 0; b < 7; b++) {
                        const ulonglong2 h =
                            *(const ulonglong2*)(h1q + b * IN1_STRIDE + k4 * 4);
                        fma2(accA[b], wa.x, h.x);
                        fma2(accA[b], wa.y, h.y);
                        fma2(accB[b], wbv.x, h.x);
                        fma2(accB[b], wbv.y, h.y);
                    }
                }
#pragma unroll 4
                for (int k4 = 0; k4 < NH2 / 4; k4++) {                  // 8
                    const ulonglong2 wa = *(const ulonglong2*)(wA + NH1 + k4 * 4);
                    const ulonglong2 wbv = *(const ulonglong2*)(wB + NH1 + k4 * 4);
#pragma unroll
                    for (int b = 0; b < 7; b++) {
                        const ulonglong2 h =
                            *(const ulonglong2*)(h2q + b * H2_STRIDE + k4 * 4);
                        fma2(accA[b], wa.x, h.x);
                        fma2(accA[b], wa.y, h.y);
                        fma2(accB[b], wbv.x, h.x);
                        fma2(accB[b], wbv.y, h.y);
                    }
                }
                float* h2w = sH2 + ((t + 1) & 1) * H2_BUF + (qf * 7) * H2_STRIDE; // h2(t-1)
#pragma unroll
                for (int j = 0; j < 7; j++) {
                    const float vA = sigm_(pairsum(accA[j]));             // i or f
                    const float vBr = pairsum(accB[j]);
                    const float vB = (sf == 0) ? tanh_(vBr) : sigm_(vBr); // g or o
                    const float pA = __shfl_xor_sync(0xffffffffu, vA, 8);
                    const float pB = __shfl_xor_sync(0xffffffffu, vB, 8);
                    const float i_ = (sf == 0) ? vA : pA;
                    const float f_ = (sf == 0) ? pA : vA;
                    const float g_ = (sf == 0) ? vB : pB;
                    const float o_ = (sf == 0) ? pB : vB;
                    c2r[j] = fmaf(f_, c2r[j], i_ * g_);
                    const float h = o_ * tanh_(c2r[j]);
                    if ((j & 1) == sf)
                        h2w[j * H2_STRIDE + uf] = h;
                }
            }
        }

        __syncthreads();                 // single per-step barrier
    }

    // ---- final FC: out[b] = h2(T-1) . Wfc + bfc ----
    // h2(T-1) written at iteration t=T into buffer ((T+1)&1)
    if (tid < NB) {
        const int bg = b0 + tid;
        if (bg < BATCH) {
            const float* h2f = sH2 + ((T_STEPS + 1) & 1) * H2_BUF
                                   + tid * H2_STRIDE;
            float s = bfc[0];
#pragma unroll
            for (int u = 0; u < NH2; u++)
                s = fmaf(h2f[u], sWfc[u], s);
            out[bg] = s;
        }
    }
}

extern "C" void kernel_launch(void* const* d_in, const int* in_sizes, int n_in,
                              void* d_out, int out_size)
{
    const float* x    = (const float*)d_in[0];
    const float* Wih1 = (const float*)d_in[1];
    const float* Whh1 = (const float*)d_in[2];
    const float* bih1 = (const float*)d_in[3];
    const float* bhh1 = (const float*)d_in[4];
    const float* Wih2 = (const float*)d_in[5];
    const float* Whh2 = (const float*)d_in[6];
    const float* bih2 = (const float*)d_in[7];
    const float* bhh2 = (const float*)d_in[8];
    const float* Wfc  = (const float*)d_in[9];
    const float* bfc  = (const float*)d_in[10];
    float* out = (float*)d_out;

    const size_t smem_bytes = SMEM_FLOATS * sizeof(float);  // ~166 KB
    cudaFuncSetAttribute(lstm2_fused_kernel,
                         cudaFuncAttributeMaxDynamicSharedMemorySize,
                         (int)smem_bytes);

    lstm2_fused_kernel<<<GRID, BLK, smem_bytes>>>(
        x, Wih1, Whh1, bih1, bhh1, Wih2, Whh2, bih2, bhh2, Wfc, bfc, out);
}